// round 14
// baseline (speedup 1.0000x reference)
#include <cuda_runtime.h>

#define EMB   128
#define EDGEF 32
#define NSTEP 3
#define NG    256
#define MAXN  50000

// Encoded -inf for the monotonic float->uint max ordering (see enc/dec below)
#define ENC_NEGINF 0x007fffffu

// ---------------- scratch (device globals; referenced directly) --------------
__device__ unsigned g_agg [MAXN*EMB];
__device__ float    g_xA  [MAXN*EMB];
__device__ float    g_xB  [MAXN*EMB];
__device__ float    g_feat[MAXN*EMB];
__device__ float    g_gate[MAXN];
__device__ float    g_xg0 [NG*EMB];
__device__ float    g_xg1 [NG*EMB];
__device__ float    g_pooled[NG*EMB];
__device__ int      g_starts[NG+1];

// ---------------- helpers ---------------------------------------------------
__device__ __forceinline__ float lrelu(float v){ return v > 0.f ? v : 0.01f*v; }
__device__ __forceinline__ int clampi(int v, int hi){ return v < 0 ? 0 : (v >= hi ? hi - 1 : v); }

// Monotonic order-preserving float <-> uint mapping: uint max == float max.
__device__ __forceinline__ unsigned encf(float v){
  int b = __float_as_int(v);
  return (b < 0) ? ~(unsigned)b : ((unsigned)b | 0x80000000u);
}
__device__ __forceinline__ float decf(unsigned u){
  int b = (u & 0x80000000u) ? (int)(u & 0x7fffffffu) : (int)~u;
  return __int_as_float(b);
}

// packed f32x2 FMA (PTX-only; 2x fp32 throughput, ptxas never auto-fuses)
__device__ __forceinline__ void ffma2(unsigned long long& d, unsigned long long a, unsigned long long b){
  asm("fma.rn.f32x2 %0, %1, %2, %0;" : "+l"(d) : "l"(a), "l"(b));
}
__device__ __forceinline__ float2 unpack2(unsigned long long v){
  float2 r; asm("mov.b64 {%0,%1}, %2;" : "=f"(r.x), "=f"(r.y) : "l"(v)); return r;
}

// step -> buffer selection (ping-pong over device symbols)
__device__ __forceinline__ const float* xin_of (const float* x_ext, int step){
  return step == 0 ? x_ext : (step == 1 ? g_xA : g_xB);
}
__device__ __forceinline__ float* xout_of(int step){ return step == 1 ? g_xB : g_xA; }
__device__ __forceinline__ const float* xgin_of (int step){ return (step & 1) ? g_xg1 : g_xg0; }
__device__ __forceinline__ float*       xgout_of(int step){ return (step & 1) ? g_xg0 : g_xg1; }

// ---------------- small utility kernels -------------------------------------
__global__ void fill_xg0_kernel(){
  for (int i = blockIdx.x*blockDim.x + threadIdx.x; i < NG*EMB; i += gridDim.x*blockDim.x)
    g_xg0[i] = 0.f;
}
__global__ void fill_agg_kernel(int N){
  int n = N*EMB;
  for (int i = blockIdx.x*blockDim.x + threadIdx.x; i < n; i += gridDim.x*blockDim.x)
    g_agg[i] = ENC_NEGINF;
}

// batch_ind (int32, sorted): binary-search group starts
__global__ void starts_kernel(const int* __restrict__ batch, int N){
  int g = blockIdx.x*blockDim.x + threadIdx.x;
  if (g > NG) return;
  if (g == NG){ g_starts[NG] = N; return; }
  int lo = 0, hi = N;
  while (lo < hi){ int mid = (lo+hi)>>1; if (batch[mid] < g) lo = mid+1; else hi = mid; }
  g_starts[g] = lo;
}

// ============================================================================
// Tiled GEMM core: 128 rows x 128 cols per block, 256 threads, K chunked by 32.
//  Thread tile 8 rows x 8 cols (32 f32x2 accumulators).
//  A stored value-duplicated (As[r][2k]=As[r][2k+1]=v) -> one LDS.64 yields a
//  ready (a,a) f32x2 operand (2-address broadcast per warp, conflict-free).
//  B read as LDS.64 at Bs[kk][2*cc + 32*j]: consecutive floats = valid f32x2
//  operand straight from the load pair (banks 2cc mod 32, conflict-free).
//  Inner kk: 8 LDS.64(A) + 4 LDS.64(B) + 32 FFMA2  (3 smem-B/FFMA2).
// ============================================================================
#define GEMM_INNER_LOOP8(As, Bs, r0, cc, acc)                                  \
  _Pragma("unroll")                                                            \
  for (int kk = 0; kk < 32; kk++){                                             \
    unsigned long long b0 = *(const unsigned long long*)&Bs[kk][2*cc     ];    \
    unsigned long long b1 = *(const unsigned long long*)&Bs[kk][2*cc + 32];    \
    unsigned long long b2 = *(const unsigned long long*)&Bs[kk][2*cc + 64];    \
    unsigned long long b3 = *(const unsigned long long*)&Bs[kk][2*cc + 96];    \
    _Pragma("unroll")                                                          \
    for (int i = 0; i < 8; i++){                                               \
      unsigned long long a = *(const unsigned long long*)&As[r0 + i][2*kk];    \
      ffma2(acc[i][0], a, b0); ffma2(acc[i][1], a, b1);                        \
      ffma2(acc[i][2], a, b2); ffma2(acc[i][3], a, b3);                        \
    }                                                                          \
  }

// Bs fill: float2 stores, contiguous -> conflict-free, coalesced gmem.
#define GEMM_FILL_B(Bs, W, k0)                                                 \
  for (int i = tid; i < 32*(EMB/2); i += 256){                                 \
    int kk = i >> 6, cp = i & 63;                                              \
    *(float2*)&Bs[kk][2*cp] = *(const float2*)&(W)[(k0+kk)*EMB + 2*cp];        \
  }

// ---------------- edge message GEMM + scatter-max ----------------------------
// m[e,:] = lrelu([x[src[e]] | ea[e]] @ Wm + bm); agg[dst[e],:] = max over e
__global__ __launch_bounds__(256, 2) void edge_msg_kernel(
    const float* __restrict__ x_ext, const float* __restrict__ ea,
    const float* __restrict__ Wm, const float* __restrict__ bm,
    const int* __restrict__ ei, int E, int N, int step)
{
  const float* __restrict__ x = xin_of(x_ext, step);
  __shared__ __align__(16) float As[128][66];
  __shared__ __align__(16) float Bs[32][EMB];
  __shared__ int s_src[128];
  int e0  = blockIdx.x * 128;
  int tid = threadIdx.x;
  if (tid < 128){
    int e = e0 + tid;
    s_src[tid] = (e < E) ? clampi(ei[e], N) : 0;   // src row of edge e
  }
  unsigned long long acc[8][4];
  #pragma unroll
  for (int i=0;i<8;i++)
    #pragma unroll
    for (int j=0;j<4;j++) acc[i][j] = 0ull;
  int rr = tid >> 4, cc = tid & 15;
  int r0 = 8*rr;
  __syncthreads();

  #pragma unroll 1
  for (int k0 = 0; k0 < EMB + EDGEF; k0 += 32){
    for (int i = tid; i < 128*32; i += 256){
      int r = i >> 5, kk = i & 31;
      int e = e0 + r;
      float v = 0.f;
      if (e < E){
        int k = k0 + kk;
        if (k < EMB) v = x[s_src[r]*EMB + k];
        else         v = ea[e*EDGEF + (k - EMB)];
      }
      *(float2*)&As[r][2*kk] = make_float2(v, v);
    }
    GEMM_FILL_B(Bs, Wm, k0)
    __syncthreads();
    GEMM_INNER_LOOP8(As, Bs, r0, cc, acc)
    __syncthreads();
  }

  #pragma unroll
  for (int i = 0; i < 8; i++){
    int e = e0 + r0 + i;
    if (e >= E) continue;
    int d = clampi(ei[E + e], N);                  // dst row of edge e
    unsigned* arow = g_agg + d*EMB;
    #pragma unroll
    for (int j = 0; j < 4; j++){
      int c = 2*cc + 32*j;
      float2 v = unpack2(acc[i][j]);
      atomicMax(arow + c,     encf(lrelu(v.x + bm[c])));
      atomicMax(arow + c + 1, encf(lrelu(v.y + bm[c+1])));
    }
  }
}

// ---------------- node update GEMM -------------------------------------------
// x_new = lrelu([x | xg[batch] | fix(agg)] @ Wa + ba) + x
__global__ __launch_bounds__(256, 2) void node_update_kernel(
    const float* __restrict__ x_ext,
    const float* __restrict__ Wa, const float* __restrict__ ba,
    const int* __restrict__ batch, int N, int step)
{
  const float* __restrict__ x    = xin_of(x_ext, step);
  const float* __restrict__ xg   = xgin_of(step);
  float*       __restrict__ xout = xout_of(step);
  __shared__ __align__(16) float As[128][66];
  __shared__ __align__(16) float Bs[32][EMB];
  __shared__ int s_b[128];
  int n0  = blockIdx.x * 128;
  int tid = threadIdx.x;
  if (tid < 128){
    int n = n0 + tid;
    s_b[tid] = (n < N) ? clampi(batch[n], NG) : 0;
  }
  unsigned long long acc[8][4];
  #pragma unroll
  for (int i=0;i<8;i++)
    #pragma unroll
    for (int j=0;j<4;j++) acc[i][j] = 0ull;
  int rr = tid >> 4, cc = tid & 15;
  int r0 = 8*rr;
  __syncthreads();

  #pragma unroll 1
  for (int k0 = 0; k0 < 3*EMB; k0 += 32){
    for (int i = tid; i < 128*32; i += 256){
      int r = i >> 5, kk = i & 31;
      int n = n0 + r;
      float v = 0.f;
      if (n < N){
        int k = k0 + kk;
        if      (k < EMB)   v = x[n*EMB + k];
        else if (k < 2*EMB) v = xg[s_b[r]*EMB + (k - EMB)];
        else {
          unsigned u = g_agg[n*EMB + (k - 2*EMB)];
          v = (u == ENC_NEGINF) ? 0.f : decf(u);   // empty segment -> 0
        }
      }
      *(float2*)&As[r][2*kk] = make_float2(v, v);
    }
    GEMM_FILL_B(Bs, Wa, k0)
    __syncthreads();
    GEMM_INNER_LOOP8(As, Bs, r0, cc, acc)
    __syncthreads();
  }

  #pragma unroll
  for (int i = 0; i < 8; i++){
    int n = n0 + r0 + i;
    if (n >= N) continue;
    #pragma unroll
    for (int j = 0; j < 4; j++){
      int c = 2*cc + 32*j;
      float2 v = unpack2(acc[i][j]);
      xout[n*EMB + c]     = lrelu(v.x + ba[c])   + x[n*EMB + c];
      xout[n*EMB + c + 1] = lrelu(v.y + ba[c+1]) + x[n*EMB + c + 1];
    }
  }
}

// ---------------- feat GEMM: feat = lrelu(x_new @ Wfeat + bfeat) -------------
__global__ __launch_bounds__(256, 2) void feat_kernel(
    const float* __restrict__ Wf, const float* __restrict__ bf, int N, int step)
{
  const float* __restrict__ xn = xout_of(step);
  __shared__ __align__(16) float As[128][66];
  __shared__ __align__(16) float Bs[32][EMB];
  int n0  = blockIdx.x * 128;
  int tid = threadIdx.x;
  unsigned long long acc[8][4];
  #pragma unroll
  for (int i=0;i<8;i++)
    #pragma unroll
    for (int j=0;j<4;j++) acc[i][j] = 0ull;
  int rr = tid >> 4, cc = tid & 15;
  int r0 = 8*rr;

  #pragma unroll 1
  for (int k0 = 0; k0 < EMB; k0 += 32){
    for (int i = tid; i < 128*32; i += 256){
      int r = i >> 5, kk = i & 31;
      int n = n0 + r;
      float v = (n < N) ? xn[n*EMB + k0 + kk] : 0.f;
      *(float2*)&As[r][2*kk] = make_float2(v, v);
    }
    GEMM_FILL_B(Bs, Wf, k0)
    __syncthreads();
    GEMM_INNER_LOOP8(As, Bs, r0, cc, acc)
    __syncthreads();
  }

  #pragma unroll
  for (int i = 0; i < 8; i++){
    int n = n0 + r0 + i;
    if (n >= N) continue;
    #pragma unroll
    for (int j = 0; j < 4; j++){
      int c = 2*cc + 32*j;
      float2 v = unpack2(acc[i][j]);
      g_feat[n*EMB + c]     = lrelu(v.x + bf[c]);
      g_feat[n*EMB + c + 1] = lrelu(v.y + bf[c+1]);
    }
  }
}

// ---------------- gate = x_new . Wgate + bgate  (one warp per node) ----------
__global__ void gate_kernel(const float* __restrict__ Wg,
                            const float* __restrict__ bg, int N, int step){
  const float* __restrict__ xn = xout_of(step);
  int t = blockIdx.x*blockDim.x + threadIdx.x;
  int w = t >> 5, lane = t & 31;
  if (w >= N) return;
  const float* row = xn + w*EMB;
  float s = 0.f;
  #pragma unroll
  for (int k = lane; k < EMB; k += 32) s = fmaf(row[k], Wg[k], s);
  #pragma unroll
  for (int o = 16; o > 0; o >>= 1) s += __shfl_down_sync(0xffffffffu, s, o);
  if (lane == 0) g_gate[w] = s + bg[0];
}

// ---------------- per-graph softmax-attention pooling (sorted batch) ---------
__global__ void pool_kernel(){
  int g = blockIdx.x, tid = threadIdx.x;   // 128 threads
  __shared__ float red[128];
  __shared__ float sh[2];
  int s = g_starts[g], e = g_starts[g+1];
  if (s >= e){ g_pooled[g*EMB + tid] = 0.f; return; }   // uniform per block
  // pass 1: max gate
  float m = -3.402823466e38f;
  for (int n = s + tid; n < e; n += 128) m = fmaxf(m, g_gate[n]);
  red[tid] = m; __syncthreads();
  for (int o = 64; o > 0; o >>= 1){ if (tid < o) red[tid] = fmaxf(red[tid], red[tid+o]); __syncthreads(); }
  if (tid == 0) sh[0] = red[0];
  __syncthreads();
  float gm = sh[0];
  // pass 2: denom
  float sum = 0.f;
  for (int n = s + tid; n < e; n += 128) sum += expf(g_gate[n] - gm);
  red[tid] = sum; __syncthreads();
  for (int o = 64; o > 0; o >>= 1){ if (tid < o) red[tid] += red[tid+o]; __syncthreads(); }
  if (tid == 0) sh[1] = red[0];
  __syncthreads();
  float inv = 1.f / sh[1];
  // pass 3: weighted sum of feat (thread = feature column)
  float acc = 0.f;
  for (int n = s; n < e; n++)
    acc = fmaf(expf(g_gate[n] - gm), g_feat[n*EMB + tid], acc);
  g_pooled[g*EMB + tid] = acc * inv;
}

// ---------------- xg update: lrelu([pooled | xg] @ Wt + bt) + xg -------------
__global__ void xg_update_kernel(const float* __restrict__ Wt,
                                 const float* __restrict__ bt, int step)
{
  const float* __restrict__ xgin  = xgin_of(step);
  float*       __restrict__ xgout = xgout_of(step);
  int g = blockIdx.x, c = threadIdx.x;   // 128 threads
  __shared__ float a[2*EMB];
  a[c]       = g_pooled[g*EMB + c];
  a[EMB + c] = xgin[g*EMB + c];
  __syncthreads();
  float acc = bt[c];
  #pragma unroll 8
  for (int k = 0; k < 2*EMB; k++) acc = fmaf(a[k], Wt[k*EMB + c], acc);
  xgout[g*EMB + c] = lrelu(acc) + a[EMB + c];
}

// ---------------- output assembly: [x_final (N*128) | xg_final (256*128)] ----
// After step 2: x lives in g_xA (xout_of(2)), xg lives in g_xg1 (xgout_of(2)).
__global__ void copy_out_kernel(float* __restrict__ out, int N){
  int nx = N*EMB;
  int total = nx + NG*EMB;
  for (int i = blockIdx.x*blockDim.x + threadIdx.x; i < total; i += gridDim.x*blockDim.x)
    out[i] = (i < nx) ? g_xA[i] : g_xg1[i - nx];
}

// ---------------- host: pure kernel launches (graph-capturable) --------------
extern "C" void kernel_launch(void* const* d_in, const int* in_sizes, int n_in,
                              void* d_out, int out_size)
{
  const float* x     = (const float*)d_in[0];
  const float* ea    = (const float*)d_in[1];
  const float* Wm    = (const float*)d_in[2];
  const float* bm    = (const float*)d_in[3];
  const float* Wa    = (const float*)d_in[4];
  const float* ba    = (const float*)d_in[5];
  const float* Wg    = (const float*)d_in[6];
  const float* bg    = (const float*)d_in[7];
  const float* Wf    = (const float*)d_in[8];
  const float* bf    = (const float*)d_in[9];
  const float* Wt    = (const float*)d_in[10];
  const float* bt    = (const float*)d_in[11];
  const int*   ei    = (const int*)d_in[12];   // edge_index: int32
  const int*   batch = (const int*)d_in[13];   // batch_ind:  int32, sorted
  int N = in_sizes[0] / EMB;
  int E = in_sizes[1] / EDGEF;

  fill_xg0_kernel<<<32, 256>>>();            // xg init = zeros
  starts_kernel<<<2, 160>>>(batch, N);       // per-graph node ranges (257 needed)

  for (int s = 0; s < NSTEP; s++){
    fill_agg_kernel   <<<2048, 256>>>(N);
    edge_msg_kernel   <<<(E+127)/128, 256>>>(x, ea, Wm + s*(EMB+EDGEF)*EMB, bm + s*EMB, ei, E, N, s);
    node_update_kernel<<<(N+127)/128, 256>>>(x, Wa + s*3*EMB*EMB, ba + s*EMB, batch, N, s);
    feat_kernel       <<<(N+127)/128, 256>>>(Wf + s*EMB*EMB, bf + s*EMB, N, s);
    gate_kernel       <<<(N+7)/8,   256>>>(Wg + s*EMB, bg + s, N, s);
    pool_kernel       <<<NG, 128>>>();
    xg_update_kernel  <<<NG, EMB>>>(Wt + s*2*EMB*EMB, bt + s*EMB, s);
  }
  copy_out_kernel<<<4096, 256>>>((float*)d_out, N);
  (void)n_in; (void)out_size;
}

// round 15
// speedup vs baseline: 1.8341x; 1.8341x over previous
#include <cuda_runtime.h>

#define EMB   128
#define EDGEF 32
#define NSTEP 3
#define NG    256
#define MAXN  50000

// Encoded -inf for the monotonic float->uint max ordering (see enc/dec below)
#define ENC_NEGINF 0x007fffffu

// ---------------- scratch (device globals; referenced directly) --------------
__device__ unsigned g_agg [MAXN*EMB];
__device__ float    g_y   [MAXN*EMB];   // x @ Wm[0:128] per step
__device__ float    g_xA  [MAXN*EMB];
__device__ float    g_xB  [MAXN*EMB];
__device__ float    g_feat[MAXN*EMB];
__device__ float    g_gate[MAXN];
__device__ float    g_xg0 [NG*EMB];
__device__ float    g_xg1 [NG*EMB];
__device__ float    g_xgw [NG*EMB];     // xg @ Wa[128:256] per step
__device__ float    g_pooled[NG*EMB];
__device__ int      g_starts[NG+1];

// ---------------- helpers ---------------------------------------------------
__device__ __forceinline__ float lrelu(float v){ return v > 0.f ? v : 0.01f*v; }
__device__ __forceinline__ int clampi(int v, int hi){ return v < 0 ? 0 : (v >= hi ? hi - 1 : v); }

// Monotonic order-preserving float <-> uint mapping: uint max == float max.
__device__ __forceinline__ unsigned encf(float v){
  int b = __float_as_int(v);
  return (b < 0) ? ~(unsigned)b : ((unsigned)b | 0x80000000u);
}
__device__ __forceinline__ float decf(unsigned u){
  int b = (u & 0x80000000u) ? (int)(u & 0x7fffffffu) : (int)~u;
  return __int_as_float(b);
}

// packed f32x2 FMA (PTX-only; 2x fp32 throughput, ptxas never auto-fuses)
__device__ __forceinline__ void ffma2(unsigned long long& d, unsigned long long a, unsigned long long b){
  asm("fma.rn.f32x2 %0, %1, %2, %0;" : "+l"(d) : "l"(a), "l"(b));
}
__device__ __forceinline__ float2 unpack2(unsigned long long v){
  float2 r; asm("mov.b64 {%0,%1}, %2;" : "=f"(r.x), "=f"(r.y) : "l"(v)); return r;
}

// step -> buffer selection (ping-pong over device symbols)
__device__ __forceinline__ const float* xin_of (const float* x_ext, int step){
  return step == 0 ? x_ext : (step == 1 ? g_xA : g_xB);
}
__device__ __forceinline__ float* xout_of(int step){ return step == 1 ? g_xB : g_xA; }
__device__ __forceinline__ const float* xgin_of (int step){ return (step & 1) ? g_xg1 : g_xg0; }
__device__ __forceinline__ float*       xgout_of(int step){ return (step & 1) ? g_xg0 : g_xg1; }

// ---------------- small utility kernels -------------------------------------
__global__ void fill_xg0_kernel(){
  for (int i = blockIdx.x*blockDim.x + threadIdx.x; i < NG*EMB; i += gridDim.x*blockDim.x)
    g_xg0[i] = 0.f;
}
__global__ void fill_agg_kernel(int N){
  uint4 v = make_uint4(ENC_NEGINF, ENC_NEGINF, ENC_NEGINF, ENC_NEGINF);
  int n = N*EMB/4;
  uint4* p = (uint4*)g_agg;
  for (int i = blockIdx.x*blockDim.x + threadIdx.x; i < n; i += gridDim.x*blockDim.x)
    p[i] = v;
}

// batch_ind (int32, sorted): binary-search group starts
__global__ void starts_kernel(const int* __restrict__ batch, int N){
  int g = blockIdx.x*blockDim.x + threadIdx.x;
  if (g > NG) return;
  if (g == NG){ g_starts[NG] = N; return; }
  int lo = 0, hi = N;
  while (lo < hi){ int mid = (lo+hi)>>1; if (batch[mid] < g) lo = mid+1; else hi = mid; }
  g_starts[g] = lo;
}

// ============================================================================
// Tiled GEMM core (R13-proven): 64 rows x 128 cols, 256 threads, K chunk 32.
//  Thread tile 4 rows x 8 cols. A value-duplicated -> LDS.64 gives (a,a) f32x2.
//  B LDS.64 at Bs[kk][2*cc + 32*j] -> register pair is a valid f32x2 operand.
//  All accesses bank-conflict-free.
// ============================================================================
#define GEMM_INNER_LOOP(As, Bs, r0, cc, acc)                                   \
  _Pragma("unroll")                                                            \
  for (int kk = 0; kk < 32; kk++){                                             \
    unsigned long long a0 = *(const unsigned long long*)&As[r0    ][2*kk];     \
    unsigned long long a1 = *(const unsigned long long*)&As[r0 + 1][2*kk];     \
    unsigned long long a2 = *(const unsigned long long*)&As[r0 + 2][2*kk];     \
    unsigned long long a3 = *(const unsigned long long*)&As[r0 + 3][2*kk];     \
    unsigned long long b0 = *(const unsigned long long*)&Bs[kk][2*cc     ];    \
    unsigned long long b1 = *(const unsigned long long*)&Bs[kk][2*cc + 32];    \
    unsigned long long b2 = *(const unsigned long long*)&Bs[kk][2*cc + 64];    \
    unsigned long long b3 = *(const unsigned long long*)&Bs[kk][2*cc + 96];    \
    ffma2(acc[0][0], a0, b0); ffma2(acc[0][1], a0, b1);                        \
    ffma2(acc[0][2], a0, b2); ffma2(acc[0][3], a0, b3);                        \
    ffma2(acc[1][0], a1, b0); ffma2(acc[1][1], a1, b1);                        \
    ffma2(acc[1][2], a1, b2); ffma2(acc[1][3], a1, b3);                        \
    ffma2(acc[2][0], a2, b0); ffma2(acc[2][1], a2, b1);                        \
    ffma2(acc[2][2], a2, b2); ffma2(acc[2][3], a2, b3);                        \
    ffma2(acc[3][0], a3, b0); ffma2(acc[3][1], a3, b1);                        \
    ffma2(acc[3][2], a3, b2); ffma2(acc[3][3], a3, b3);                        \
  }

#define GEMM_DECL_ACC                                                          \
  unsigned long long acc[4][4];                                                \
  _Pragma("unroll")                                                            \
  for (int i=0;i<4;i++){ _Pragma("unroll") for (int j=0;j<4;j++) acc[i][j]=0ull; }

// Bs fill from weight row `wrow(kk)`: float2 stores, conflict-free, coalesced.
#define GEMM_FILL_B_ROWS(Bs, W, ROWBASE)                                       \
  for (int i = tid; i < 32*(EMB/2); i += 256){                                 \
    int kk = i >> 6, cp = i & 63;                                              \
    *(float2*)&Bs[kk][2*cp] = *(const float2*)&(W)[(ROWBASE + kk)*EMB + 2*cp]; \
  }

// ---------------- y = x @ Wm[0:128]  (per-node, K=128, no bias/act) ----------
__global__ __launch_bounds__(256) void y_kernel(
    const float* __restrict__ x_ext, const float* __restrict__ Wm,
    int N, int step)
{
  const float* __restrict__ xn = xin_of(x_ext, step);
  __shared__ __align__(16) float As[64][66];
  __shared__ __align__(16) float Bs[32][EMB];
  int n0  = blockIdx.x * 64;
  int tid = threadIdx.x;
  GEMM_DECL_ACC
  int rr = tid >> 4, cc = tid & 15;
  int r0 = 4*rr;

  #pragma unroll 1
  for (int k0 = 0; k0 < EMB; k0 += 32){
    for (int i = tid; i < 64*32; i += 256){
      int r = i >> 5, kk = i & 31;
      int n = n0 + r;
      float v = (n < N) ? xn[n*EMB + k0 + kk] : 0.f;
      *(float2*)&As[r][2*kk] = make_float2(v, v);
    }
    GEMM_FILL_B_ROWS(Bs, Wm, k0)
    __syncthreads();
    GEMM_INNER_LOOP(As, Bs, r0, cc, acc)
    __syncthreads();
  }

  #pragma unroll
  for (int i = 0; i < 4; i++){
    int n = n0 + r0 + i;
    if (n >= N) continue;
    #pragma unroll
    for (int j = 0; j < 4; j++){
      int c = 2*cc + 32*j;
      float2 v = unpack2(acc[i][j]);
      *(float2*)&g_y[n*EMB + c] = v;
    }
  }
}

// ---------------- edge message: ea @ Wm[128:160] + y[src] -> scatter-max -----
// m[e,:] = lrelu(y[src[e]] + ea[e]@Wm2 + bm); agg[dst[e],:] = max over e
__global__ __launch_bounds__(256) void edge_msg_kernel(
    const float* __restrict__ ea,
    const float* __restrict__ Wm, const float* __restrict__ bm,
    const int* __restrict__ ei, int E, int N)
{
  __shared__ __align__(16) float As[64][66];
  __shared__ __align__(16) float Bs[32][EMB];
  __shared__ int s_src[64];
  int e0  = blockIdx.x * 64;
  int tid = threadIdx.x;
  if (tid < 64){
    int e = e0 + tid;
    s_src[tid] = (e < E) ? clampi(ei[e], N) : 0;
  }
  GEMM_DECL_ACC
  int rr = tid >> 4, cc = tid & 15;
  int r0 = 4*rr;

  // single K chunk: ea is 32 wide
  for (int i = tid; i < 64*32; i += 256){
    int r = i >> 5, kk = i & 31;
    int e = e0 + r;
    float v = (e < E) ? ea[e*EDGEF + kk] : 0.f;
    *(float2*)&As[r][2*kk] = make_float2(v, v);
  }
  GEMM_FILL_B_ROWS(Bs, Wm, EMB)   // Wm rows 128..159
  __syncthreads();
  GEMM_INNER_LOOP(As, Bs, r0, cc, acc)

  #pragma unroll
  for (int i = 0; i < 4; i++){
    int e = e0 + r0 + i;
    if (e >= E) continue;
    int src = s_src[r0 + i];
    int d = clampi(ei[E + e], N);
    const float* yrow = g_y + src*EMB;
    unsigned* arow = g_agg + d*EMB;
    #pragma unroll
    for (int j = 0; j < 4; j++){
      int c = 2*cc + 32*j;
      float2 yv = *(const float2*)&yrow[c];
      float2 v = unpack2(acc[i][j]);
      atomicMax(arow + c,     encf(lrelu(v.x + yv.x + bm[c])));
      atomicMax(arow + c + 1, encf(lrelu(v.y + yv.y + bm[c+1])));
    }
  }
}

// ---------------- xgW = xg @ Wa[128:256]  (256 rows, tiny) -------------------
__global__ void xgw_kernel(const float* __restrict__ Wa, int step){
  const float* __restrict__ xgin = xgin_of(step);
  int g = blockIdx.x, c = threadIdx.x;   // 128 threads
  __shared__ float a[EMB];
  a[c] = xgin[g*EMB + c];
  __syncthreads();
  float acc = 0.f;
  #pragma unroll 8
  for (int k = 0; k < EMB; k++) acc = fmaf(a[k], Wa[(EMB + k)*EMB + c], acc);
  g_xgw[g*EMB + c] = acc;
}

// ---------------- node update: x@Wa1 + agg@Wa3 (+xgW gather) -----------------
// x_new = lrelu(x@Wa[0:128] + xgW[batch] + fix(agg)@Wa[256:384] + ba) + x
__global__ __launch_bounds__(256) void node_update_kernel(
    const float* __restrict__ x_ext,
    const float* __restrict__ Wa, const float* __restrict__ ba,
    const int* __restrict__ batch, int N, int step)
{
  const float* __restrict__ x    = xin_of(x_ext, step);
  float*       __restrict__ xout = xout_of(step);
  __shared__ __align__(16) float As[64][66];
  __shared__ __align__(16) float Bs[32][EMB];
  __shared__ int s_b[64];
  int n0  = blockIdx.x * 64;
  int tid = threadIdx.x;
  if (tid < 64){
    int n = n0 + tid;
    s_b[tid] = (n < N) ? clampi(batch[n], NG) : 0;
  }
  GEMM_DECL_ACC
  int rr = tid >> 4, cc = tid & 15;
  int r0 = 4*rr;
  __syncthreads();

  // K = 256: k<128 -> x (Wa rows 0..127); k>=128 -> agg (Wa rows 256..383)
  #pragma unroll 1
  for (int k0 = 0; k0 < 2*EMB; k0 += 32){
    for (int i = tid; i < 64*32; i += 256){
      int r = i >> 5, kk = i & 31;
      int n = n0 + r;
      float v = 0.f;
      if (n < N){
        int k = k0 + kk;
        if (k < EMB) v = x[n*EMB + k];
        else {
          unsigned u = g_agg[n*EMB + (k - EMB)];
          v = (u == ENC_NEGINF) ? 0.f : decf(u);   // empty segment -> 0
        }
      }
      *(float2*)&As[r][2*kk] = make_float2(v, v);
    }
    int wbase = (k0 < EMB) ? k0 : (k0 + EMB);      // skip xg rows 128..255
    GEMM_FILL_B_ROWS(Bs, Wa, wbase)
    __syncthreads();
    GEMM_INNER_LOOP(As, Bs, r0, cc, acc)
    __syncthreads();
  }

  #pragma unroll
  for (int i = 0; i < 4; i++){
    int n = n0 + r0 + i;
    if (n >= N) continue;
    const float* xgwrow = g_xgw + s_b[r0 + i]*EMB;
    #pragma unroll
    for (int j = 0; j < 4; j++){
      int c = 2*cc + 32*j;
      float2 gv = *(const float2*)&xgwrow[c];
      float2 v = unpack2(acc[i][j]);
      xout[n*EMB + c]     = lrelu(v.x + gv.x + ba[c])   + x[n*EMB + c];
      xout[n*EMB + c + 1] = lrelu(v.y + gv.y + ba[c+1]) + x[n*EMB + c + 1];
    }
  }
}

// ---------------- feat GEMM: feat = lrelu(x_new @ Wfeat + bfeat) -------------
__global__ __launch_bounds__(256) void feat_kernel(
    const float* __restrict__ Wf, const float* __restrict__ bf, int N, int step)
{
  const float* __restrict__ xn = xout_of(step);
  __shared__ __align__(16) float As[64][66];
  __shared__ __align__(16) float Bs[32][EMB];
  int n0  = blockIdx.x * 64;
  int tid = threadIdx.x;
  GEMM_DECL_ACC
  int rr = tid >> 4, cc = tid & 15;
  int r0 = 4*rr;

  #pragma unroll 1
  for (int k0 = 0; k0 < EMB; k0 += 32){
    for (int i = tid; i < 64*32; i += 256){
      int r = i >> 5, kk = i & 31;
      int n = n0 + r;
      float v = (n < N) ? xn[n*EMB + k0 + kk] : 0.f;
      *(float2*)&As[r][2*kk] = make_float2(v, v);
    }
    GEMM_FILL_B_ROWS(Bs, Wf, k0)
    __syncthreads();
    GEMM_INNER_LOOP(As, Bs, r0, cc, acc)
    __syncthreads();
  }

  #pragma unroll
  for (int i = 0; i < 4; i++){
    int n = n0 + r0 + i;
    if (n >= N) continue;
    #pragma unroll
    for (int j = 0; j < 4; j++){
      int c = 2*cc + 32*j;
      float2 v = unpack2(acc[i][j]);
      g_feat[n*EMB + c]     = lrelu(v.x + bf[c]);
      g_feat[n*EMB + c + 1] = lrelu(v.y + bf[c+1]);
    }
  }
}

// ---------------- gate = x_new . Wgate + bgate  (one warp per node) ----------
__global__ void gate_kernel(const float* __restrict__ Wg,
                            const float* __restrict__ bg, int N, int step){
  const float* __restrict__ xn = xout_of(step);
  int t = blockIdx.x*blockDim.x + threadIdx.x;
  int w = t >> 5, lane = t & 31;
  if (w >= N) return;
  const float* row = xn + w*EMB;
  float s = 0.f;
  #pragma unroll
  for (int k = lane; k < EMB; k += 32) s = fmaf(row[k], Wg[k], s);
  #pragma unroll
  for (int o = 16; o > 0; o >>= 1) s += __shfl_down_sync(0xffffffffu, s, o);
  if (lane == 0) g_gate[w] = s + bg[0];
}

// ---------------- per-graph softmax-attention pooling (sorted batch) ---------
__global__ void pool_kernel(){
  int g = blockIdx.x, tid = threadIdx.x;   // 128 threads
  __shared__ float red[128];
  __shared__ float sh[2];
  int s = g_starts[g], e = g_starts[g+1];
  if (s >= e){ g_pooled[g*EMB + tid] = 0.f; return; }   // uniform per block
  // pass 1: max gate
  float m = -3.402823466e38f;
  for (int n = s + tid; n < e; n += 128) m = fmaxf(m, g_gate[n]);
  red[tid] = m; __syncthreads();
  for (int o = 64; o > 0; o >>= 1){ if (tid < o) red[tid] = fmaxf(red[tid], red[tid+o]); __syncthreads(); }
  if (tid == 0) sh[0] = red[0];
  __syncthreads();
  float gm = sh[0];
  // pass 2: denom
  float sum = 0.f;
  for (int n = s + tid; n < e; n += 128) sum += expf(g_gate[n] - gm);
  red[tid] = sum; __syncthreads();
  for (int o = 64; o > 0; o >>= 1){ if (tid < o) red[tid] += red[tid+o]; __syncthreads(); }
  if (tid == 0) sh[1] = red[0];
  __syncthreads();
  float inv = 1.f / sh[1];
  // pass 3: weighted sum of feat (thread = feature column)
  float acc = 0.f;
  for (int n = s; n < e; n++)
    acc = fmaf(expf(g_gate[n] - gm), g_feat[n*EMB + tid], acc);
  g_pooled[g*EMB + tid] = acc * inv;
}

// ---------------- xg update: lrelu([pooled | xg] @ Wt + bt) + xg -------------
__global__ void xg_update_kernel(const float* __restrict__ Wt,
                                 const float* __restrict__ bt, int step)
{
  const float* __restrict__ xgin  = xgin_of(step);
  float*       __restrict__ xgout = xgout_of(step);
  int g = blockIdx.x, c = threadIdx.x;   // 128 threads
  __shared__ float a[2*EMB];
  a[c]       = g_pooled[g*EMB + c];
  a[EMB + c] = xgin[g*EMB + c];
  __syncthreads();
  float acc = bt[c];
  #pragma unroll 8
  for (int k = 0; k < 2*EMB; k++) acc = fmaf(a[k], Wt[k*EMB + c], acc);
  xgout[g*EMB + c] = lrelu(acc) + a[EMB + c];
}

// ---------------- output assembly: [x_final (N*128) | xg_final (256*128)] ----
// After step 2: x lives in g_xA (xout_of(2)), xg lives in g_xg1 (xgout_of(2)).
__global__ void copy_out_kernel(float* __restrict__ out, int N){
  int nx = N*EMB;
  int total = nx + NG*EMB;
  for (int i = blockIdx.x*blockDim.x + threadIdx.x; i < total; i += gridDim.x*blockDim.x)
    out[i] = (i < nx) ? g_xA[i] : g_xg1[i - nx];
}

// ---------------- host: pure kernel launches (graph-capturable) --------------
extern "C" void kernel_launch(void* const* d_in, const int* in_sizes, int n_in,
                              void* d_out, int out_size)
{
  const float* x     = (const float*)d_in[0];
  const float* ea    = (const float*)d_in[1];
  const float* Wm    = (const float*)d_in[2];
  const float* bm    = (const float*)d_in[3];
  const float* Wa    = (const float*)d_in[4];
  const float* ba    = (const float*)d_in[5];
  const float* Wg    = (const float*)d_in[6];
  const float* bg    = (const float*)d_in[7];
  const float* Wf    = (const float*)d_in[8];
  const float* bf    = (const float*)d_in[9];
  const float* Wt    = (const float*)d_in[10];
  const float* bt    = (const float*)d_in[11];
  const int*   ei    = (const int*)d_in[12];   // edge_index: int32
  const int*   batch = (const int*)d_in[13];   // batch_ind:  int32, sorted
  int N = in_sizes[0] / EMB;
  int E = in_sizes[1] / EDGEF;

  fill_xg0_kernel<<<32, 256>>>();            // xg init = zeros
  starts_kernel<<<2, 160>>>(batch, N);       // per-graph node ranges (257 needed)

  for (int s = 0; s < NSTEP; s++){
    fill_agg_kernel   <<<1024, 256>>>(N);
    y_kernel          <<<(N+63)/64, 256>>>(x, Wm + s*(EMB+EDGEF)*EMB, N, s);
    edge_msg_kernel   <<<(E+63)/64, 256>>>(ea, Wm + s*(EMB+EDGEF)*EMB, bm + s*EMB, ei, E, N);
    xgw_kernel        <<<NG, EMB>>>(Wa + s*3*EMB*EMB, s);
    node_update_kernel<<<(N+63)/64, 256>>>(x, Wa + s*3*EMB*EMB, ba + s*EMB, batch, N, s);
    feat_kernel       <<<(N+63)/64, 256>>>(Wf + s*EMB*EMB, bf + s*EMB, N, s);
    gate_kernel       <<<(N+7)/8,   256>>>(Wg + s*EMB, bg + s, N, s);
    pool_kernel       <<<NG, 128>>>();
    xg_update_kernel  <<<NG, EMB>>>(Wt + s*2*EMB*EMB, bt + s*EMB, s);
  }
  copy_out_kernel<<<4096, 256>>>((float*)d_out, N);
  (void)n_in; (void)out_size;
}